// round 10
// baseline (speedup 1.0000x reference)
#include <cuda_runtime.h>
#include <math.h>

// Scratch (allocation-free rule: __device__ globals)
__device__ float g_A[8 * 256];          // combined DCT-mask-iDCT-resize operator
__device__ float g_dct[128 * 3 * 64];   // dct branch input, (b,c,8,8)
__device__ float g_grad[128 * 3 * 64];  // grad branch input, (b,c,8,8)
__device__ float g_part[1024][5];       // per (b, chgroup) partials

// ---------------------------------------------------------------------------
// Setup (R5 form): Chebyshev recurrence, 1 cospif + FMA chain.
// grid=8, block=256
// ---------------------------------------------------------------------------
__global__ void setupA_kernel() {
    __shared__ float Rf[32];
    const int o = blockIdx.x;
    const int j = threadIdx.x;
    const float r0 = (float)(32 * o + 15), r1 = (float)(32 * o + 16);
    if (j < 25) {
        float sk = (j == 0) ? sqrtf(1.0f / 256.0f) : sqrtf(2.0f / 256.0f);
        float si = sqrtf(2.0f / 256.0f);
        float tw = (float)(2 * j + 1) * (1.0f / 512.0f);   // exact
        float c0 = cospif(tw * r0);
        float c1 = cospif(tw * r1);
        Rf[j] = 0.5f * si * sk * (c0 + c1);
    }
    __syncthreads();
    const float th = (float)(2 * j + 1) * (1.0f / 512.0f);  // exact
    float cp = cospif(th);
    const float twoc = 2.0f * cp;
    float cpp = 1.0f;
    float a = fmaf(Rf[1], cp, Rf[0]);
#pragma unroll
    for (int k = 2; k < 25; k++) {
        float ck = fmaf(twoc, cp, -cpp);
        a = fmaf(Rf[k], ck, a);
        cpp = cp; cp = ck;
    }
    g_A[o * 256 + j] = a;
}

// ---------------------------------------------------------------------------
// Kernel 1 (R5 form, byte-identical): dct_in = A x A^T and sampled Sobel.
// grid = 384, block = 256 (4 teams x 64 threads)
// ---------------------------------------------------------------------------
__global__ void __launch_bounds__(256) dct_grad_kernel(const float* __restrict__ x) {
    __shared__ float As[256][8];       // As[m][o] = A[o][m]   (8 KB)
    __shared__ float Tp[4][8][256];    // team partials, later aliased as Ts (32 KB)

    const int tid = threadIdx.x;
    const int blk = blockIdx.x;
    const float* __restrict__ xc = x + (size_t)blk * 65536;

#pragma unroll
    for (int o = 0; o < 8; o++) As[tid][o] = g_A[o * 256 + tid];
    __syncthreads();

    const int team = tid >> 6;         // 0..3 -> rows 64*team .. 64*team+63
    const int t64  = tid & 63;         // 0..63 -> columns 4*t64 .. 4*t64+3

    float acc[8][4];
#pragma unroll
    for (int o = 0; o < 8; o++)
#pragma unroll
        for (int c = 0; c < 4; c++) acc[o][c] = 0.0f;

    const int mbase = team * 64;
#pragma unroll 4
    for (int mm = 0; mm < 64; mm++) {
        const int m = mbase + mm;
        float4 xv = reinterpret_cast<const float4*>(xc + (size_t)m * 256)[t64];
        float4 a0 = *reinterpret_cast<const float4*>(&As[m][0]);
        float4 a1 = *reinterpret_cast<const float4*>(&As[m][4]);
        acc[0][0] = fmaf(a0.x, xv.x, acc[0][0]);
        acc[0][1] = fmaf(a0.x, xv.y, acc[0][1]);
        acc[0][2] = fmaf(a0.x, xv.z, acc[0][2]);
        acc[0][3] = fmaf(a0.x, xv.w, acc[0][3]);
        acc[1][0] = fmaf(a0.y, xv.x, acc[1][0]);
        acc[1][1] = fmaf(a0.y, xv.y, acc[1][1]);
        acc[1][2] = fmaf(a0.y, xv.z, acc[1][2]);
        acc[1][3] = fmaf(a0.y, xv.w, acc[1][3]);
        acc[2][0] = fmaf(a0.z, xv.x, acc[2][0]);
        acc[2][1] = fmaf(a0.z, xv.y, acc[2][1]);
        acc[2][2] = fmaf(a0.z, xv.z, acc[2][2]);
        acc[2][3] = fmaf(a0.z, xv.w, acc[2][3]);
        acc[3][0] = fmaf(a0.w, xv.x, acc[3][0]);
        acc[3][1] = fmaf(a0.w, xv.y, acc[3][1]);
        acc[3][2] = fmaf(a0.w, xv.z, acc[3][2]);
        acc[3][3] = fmaf(a0.w, xv.w, acc[3][3]);
        acc[4][0] = fmaf(a1.x, xv.x, acc[4][0]);
        acc[4][1] = fmaf(a1.x, xv.y, acc[4][1]);
        acc[4][2] = fmaf(a1.x, xv.z, acc[4][2]);
        acc[4][3] = fmaf(a1.x, xv.w, acc[4][3]);
        acc[5][0] = fmaf(a1.y, xv.x, acc[5][0]);
        acc[5][1] = fmaf(a1.y, xv.y, acc[5][1]);
        acc[5][2] = fmaf(a1.y, xv.z, acc[5][2]);
        acc[5][3] = fmaf(a1.y, xv.w, acc[5][3]);
        acc[6][0] = fmaf(a1.z, xv.x, acc[6][0]);
        acc[6][1] = fmaf(a1.z, xv.y, acc[6][1]);
        acc[6][2] = fmaf(a1.z, xv.z, acc[6][2]);
        acc[6][3] = fmaf(a1.z, xv.w, acc[6][3]);
        acc[7][0] = fmaf(a1.w, xv.x, acc[7][0]);
        acc[7][1] = fmaf(a1.w, xv.y, acc[7][1]);
        acc[7][2] = fmaf(a1.w, xv.z, acc[7][2]);
        acc[7][3] = fmaf(a1.w, xv.w, acc[7][3]);
    }
#pragma unroll
    for (int o = 0; o < 8; o++)
        *reinterpret_cast<float4*>(&Tp[team][o][t64 * 4]) =
            make_float4(acc[o][0], acc[o][1], acc[o][2], acc[o][3]);
    __syncthreads();

    // Reduce 4 team partials; alias Ts over Tp[0] (thread t only touches col t).
    float* TsF = &Tp[0][0][0];   // Ts[o][c] = TsF[o*256 + c]
    {
        float s[8];
#pragma unroll
        for (int o = 0; o < 8; o++)
            s[o] = Tp[0][o][tid] + Tp[1][o][tid] + Tp[2][o][tid] + Tp[3][o][tid];
#pragma unroll
        for (int o = 0; o < 8; o++) TsF[o * 256 + tid] = s[o];
    }
    __syncthreads();

    if (tid < 64) {
        // out[oy][ox] = sum_j Ts[oy][j] * A[ox][j]
        const int oy = tid >> 3, ox = tid & 7;
        const float* tsr = TsF + oy * 256;
        float s = 0.0f;
#pragma unroll 8
        for (int j = 0; j < 256; j++)
            s = fmaf(tsr[j], As[j][ox], s);
        g_dct[blk * 64 + tid] = s;
    } else if (tid < 128) {
        // Sobel-magnitude, 2x2 average at (32oy+15..16, 32ox+15..16)
        const int cl = tid - 64;
        const int r = 32 * (cl >> 3) + 15;
        const int c = 32 * (cl & 7) + 15;
        float p[4][4];
#pragma unroll
        for (int a = 0; a < 4; a++)
#pragma unroll
            for (int b = 0; b < 4; b++)
                p[a][b] = xc[(r - 1 + a) * 256 + (c - 1 + b)];
        float gsum = 0.0f;
#pragma unroll
        for (int i = 0; i < 2; i++)
#pragma unroll
            for (int j = 0; j < 2; j++) {
                float gx = (p[i][j + 2] - p[i][j])
                         + 2.0f * (p[i + 1][j + 2] - p[i + 1][j])
                         + (p[i + 2][j + 2] - p[i + 2][j]);
                float gy = (p[i + 2][j] - p[i][j])
                         + 2.0f * (p[i + 2][j + 1] - p[i][j + 1])
                         + (p[i + 2][j + 2] - p[i][j + 2]);
                gsum += sqrtf(gx * gx + gy * gy);
            }
        g_grad[blk * 64 + cl] = 0.25f * gsum;
    }
}

// ---------------------------------------------------------------------------
// Kernel 2a: conv3x3 + BN + ReLU partials. grid = 1024 (128 b x 8 groups),
// block = 256 (8 channels x 32 threads, 2 cells each).
// ---------------------------------------------------------------------------
__global__ void __launch_bounds__(256) head_part_kernel(
    const float* __restrict__ cw_d, const float* __restrict__ cb_d,
    const float* __restrict__ bg_d, const float* __restrict__ bb_d,
    const float* __restrict__ cw_g, const float* __restrict__ cb_g,
    const float* __restrict__ bg_g, const float* __restrict__ bb_g,
    const float* __restrict__ fw, const float* __restrict__ clsw)
{
    __shared__ float tile[2][3][10][10];
    __shared__ float wsm[2][8][28];
    __shared__ float bnc[2][8][2];
    __shared__ float fws[8];
    __shared__ float wred[8][5];

    const int bidx = blockIdx.x;
    const int b = bidx >> 3, grp = bidx & 7;
    const int tid = threadIdx.x;

    for (int t = tid; t < 432; t += 256) {
        int br = t / 216, r = t % 216;
        int lc = r / 27, i = r % 27;
        const float* w = br ? cw_g : cw_d;
        wsm[br][lc][i] = w[(grp * 8 + lc) * 27 + i];
    }
    if (tid < 16) {
        int br = tid >> 3, lc = tid & 7, ch = grp * 8 + lc;
        const float rs = rsqrtf(1.0f + 1e-5f);
        float k = (br ? bg_g[ch] : bg_d[ch]) * rs;
        float bb = (br ? cb_g[ch] : cb_d[ch]) * k + (br ? bb_g[ch] : bb_d[ch]);
        bnc[br][lc][0] = k; bnc[br][lc][1] = bb;
    } else if (tid < 24) {
        fws[tid - 16] = fw[grp * 8 + (tid - 16)];
    }
    for (int t = tid; t < 600; t += 256) {
        int br = t / 300, rem = t % 300;
        int c = rem / 100, yy = (rem % 100) / 10, xx = rem % 10;
        float v = 0.0f;
        if (yy >= 1 && yy <= 8 && xx >= 1 && xx <= 8) {
            const float* src = br ? g_grad : g_dct;
            v = src[(b * 3 + c) * 64 + (yy - 1) * 8 + (xx - 1)];
        }
        tile[br][c][yy][xx] = v;
    }
    __syncthreads();

    const int lch = tid >> 5;
    const int c32 = tid & 31;
    const int ch = grp * 8 + lch;

    const float kd = bnc[0][lch][0], bd = bnc[0][lch][1];
    const float kg = bnc[1][lch][0], bg = bnc[1][lch][1];

    float s_acc = 0.f, D0 = 0.f, D1 = 0.f, G0 = 0.f, G1 = 0.f;
#pragma unroll
    for (int half = 0; half < 2; half++) {
        int cell = c32 + half * 32;
        int oy = cell >> 3, ox = cell & 7;
        float ad = 0.f, ag = 0.f;
#pragma unroll
        for (int ci = 0; ci < 3; ci++)
#pragma unroll
            for (int ky = 0; ky < 3; ky++)
#pragma unroll
                for (int kx = 0; kx < 3; kx++) {
                    float tv0 = tile[0][ci][oy + ky][ox + kx];
                    float tv1 = tile[1][ci][oy + ky][ox + kx];
                    ad = fmaf(tv0, wsm[0][lch][ci * 9 + ky * 3 + kx], ad);
                    ag = fmaf(tv1, wsm[1][lch][ci * 9 + ky * 3 + kx], ag);
                }
        float d = fmaxf(fmaf(ad, kd, bd), 0.0f);
        float g = fmaxf(fmaf(ag, kg, bg), 0.0f);
        s_acc += d + g;
        int flat = ch * 64 + cell;
        float w0 = clsw[flat], w1 = clsw[4096 + flat];
        D0 = fmaf(d, w0, D0); D1 = fmaf(d, w1, D1);
        G0 = fmaf(g, w0, G0); G1 = fmaf(g, w1, G1);
    }
    s_acc *= fws[lch];

#pragma unroll
    for (int off = 16; off > 0; off >>= 1) {
        s_acc += __shfl_down_sync(0xffffffffu, s_acc, off);
        D0 += __shfl_down_sync(0xffffffffu, D0, off);
        D1 += __shfl_down_sync(0xffffffffu, D1, off);
        G0 += __shfl_down_sync(0xffffffffu, G0, off);
        G1 += __shfl_down_sync(0xffffffffu, G1, off);
    }
    if ((tid & 31) == 0) {
        int w = tid >> 5;
        wred[w][0] = s_acc; wred[w][1] = D0; wred[w][2] = D1;
        wred[w][3] = G0; wred[w][4] = G1;
    }
    __syncthreads();
    if (tid < 5) {
        float s = 0.f;
#pragma unroll
        for (int w = 0; w < 8; w++) s += wred[w][tid];
        g_part[bidx][tid] = s;
    }
}

// ---------------------------------------------------------------------------
// Kernel 2b: gate + final combine. grid = 1, block = 128 (thread = batch).
// ---------------------------------------------------------------------------
__global__ void __launch_bounds__(128) head_final_kernel(
    const float* __restrict__ fb, const float* __restrict__ clsb,
    float* __restrict__ out)
{
    const int b = threadIdx.x;
    float a0 = 0.f, a1 = 0.f, a2 = 0.f, a3 = 0.f, a4 = 0.f;
#pragma unroll
    for (int g = 0; g < 8; g++) {
        const float* p = g_part[b * 8 + g];
        a0 += p[0]; a1 += p[1]; a2 += p[2]; a3 += p[3]; a4 += p[4];
    }
    float w = 1.0f / (1.0f + expf(-(a0 * (1.0f / 64.0f) + fb[0])));
    out[b * 2 + 0] = w * a1 + (1.0f - w) * a3 + clsb[0];
    out[b * 2 + 1] = w * a2 + (1.0f - w) * a4 + clsb[1];
}

// ---------------------------------------------------------------------------
extern "C" void kernel_launch(void* const* d_in, const int* in_sizes, int n_in,
                              void* d_out, int out_size) {
    const float* x     = (const float*)d_in[0];
    const float* cw_d  = (const float*)d_in[1];
    const float* cb_d  = (const float*)d_in[2];
    const float* bg_d  = (const float*)d_in[3];
    const float* bb_d  = (const float*)d_in[4];
    const float* cw_g  = (const float*)d_in[5];
    const float* cb_g  = (const float*)d_in[6];
    const float* bg_g  = (const float*)d_in[7];
    const float* bb_g  = (const float*)d_in[8];
    const float* fw    = (const float*)d_in[9];
    const float* fb    = (const float*)d_in[10];
    const float* clsw  = (const float*)d_in[11];
    const float* clsb  = (const float*)d_in[12];
    float* out = (float*)d_out;

    setupA_kernel<<<8, 256>>>();
    dct_grad_kernel<<<384, 256>>>(x);
    head_part_kernel<<<1024, 256>>>(cw_d, cb_d, bg_d, bb_d,
                                    cw_g, cb_g, bg_g, bb_g, fw, clsw);
    head_final_kernel<<<1, 128>>>(fb, clsb, out);
}

// round 11
// speedup vs baseline: 1.7232x; 1.7232x over previous
#include <cuda_runtime.h>
#include <math.h>

// Scratch (allocation-free rule: __device__ globals)
__device__ float g_A[8 * 256];          // combined DCT-mask-iDCT-resize operator
__device__ float g_dct[128 * 3 * 64];   // dct branch input, (b,c,8,8)
__device__ float g_grad[128 * 3 * 64];  // grad branch input, (b,c,8,8)
__device__ float g_part[5][1024];       // transposed partials: [s,D0,D1,G0,G1] x (b*8+grp)

// ---------------------------------------------------------------------------
// Setup (R5 form): Chebyshev recurrence, 1 cospif + FMA chain. grid=8, block=256
// ---------------------------------------------------------------------------
__global__ void setupA_kernel() {
    __shared__ float Rf[32];
    const int o = blockIdx.x;
    const int j = threadIdx.x;
    const float r0 = (float)(32 * o + 15), r1 = (float)(32 * o + 16);
    if (j < 25) {
        float sk = (j == 0) ? sqrtf(1.0f / 256.0f) : sqrtf(2.0f / 256.0f);
        float si = sqrtf(2.0f / 256.0f);
        float tw = (float)(2 * j + 1) * (1.0f / 512.0f);   // exact
        float c0 = cospif(tw * r0);
        float c1 = cospif(tw * r1);
        Rf[j] = 0.5f * si * sk * (c0 + c1);
    }
    __syncthreads();
    const float th = (float)(2 * j + 1) * (1.0f / 512.0f);  // exact
    float cp = cospif(th);
    const float twoc = 2.0f * cp;
    float cpp = 1.0f;
    float a = fmaf(Rf[1], cp, Rf[0]);
#pragma unroll
    for (int k = 2; k < 25; k++) {
        float ck = fmaf(twoc, cp, -cpp);
        a = fmaf(Rf[k], ck, a);
        cpp = cp; cp = ck;
    }
    g_A[o * 256 + j] = a;
}

// ---------------------------------------------------------------------------
// Kernel 1 (R5 form, unchanged): dct_in = A x A^T and sampled Sobel.
// grid = 384, block = 256 (4 teams x 64 threads)
// ---------------------------------------------------------------------------
__global__ void __launch_bounds__(256) dct_grad_kernel(const float* __restrict__ x) {
    __shared__ float As[256][8];       // As[m][o] = A[o][m]   (8 KB)
    __shared__ float Tp[4][8][256];    // team partials, later aliased as Ts (32 KB)

    const int tid = threadIdx.x;
    const int blk = blockIdx.x;
    const float* __restrict__ xc = x + (size_t)blk * 65536;

#pragma unroll
    for (int o = 0; o < 8; o++) As[tid][o] = g_A[o * 256 + tid];
    __syncthreads();

    const int team = tid >> 6;
    const int t64  = tid & 63;

    float acc[8][4];
#pragma unroll
    for (int o = 0; o < 8; o++)
#pragma unroll
        for (int c = 0; c < 4; c++) acc[o][c] = 0.0f;

    const int mbase = team * 64;
#pragma unroll 4
    for (int mm = 0; mm < 64; mm++) {
        const int m = mbase + mm;
        float4 xv = reinterpret_cast<const float4*>(xc + (size_t)m * 256)[t64];
        float4 a0 = *reinterpret_cast<const float4*>(&As[m][0]);
        float4 a1 = *reinterpret_cast<const float4*>(&As[m][4]);
        acc[0][0] = fmaf(a0.x, xv.x, acc[0][0]);
        acc[0][1] = fmaf(a0.x, xv.y, acc[0][1]);
        acc[0][2] = fmaf(a0.x, xv.z, acc[0][2]);
        acc[0][3] = fmaf(a0.x, xv.w, acc[0][3]);
        acc[1][0] = fmaf(a0.y, xv.x, acc[1][0]);
        acc[1][1] = fmaf(a0.y, xv.y, acc[1][1]);
        acc[1][2] = fmaf(a0.y, xv.z, acc[1][2]);
        acc[1][3] = fmaf(a0.y, xv.w, acc[1][3]);
        acc[2][0] = fmaf(a0.z, xv.x, acc[2][0]);
        acc[2][1] = fmaf(a0.z, xv.y, acc[2][1]);
        acc[2][2] = fmaf(a0.z, xv.z, acc[2][2]);
        acc[2][3] = fmaf(a0.z, xv.w, acc[2][3]);
        acc[3][0] = fmaf(a0.w, xv.x, acc[3][0]);
        acc[3][1] = fmaf(a0.w, xv.y, acc[3][1]);
        acc[3][2] = fmaf(a0.w, xv.z, acc[3][2]);
        acc[3][3] = fmaf(a0.w, xv.w, acc[3][3]);
        acc[4][0] = fmaf(a1.x, xv.x, acc[4][0]);
        acc[4][1] = fmaf(a1.x, xv.y, acc[4][1]);
        acc[4][2] = fmaf(a1.x, xv.z, acc[4][2]);
        acc[4][3] = fmaf(a1.x, xv.w, acc[4][3]);
        acc[5][0] = fmaf(a1.y, xv.x, acc[5][0]);
        acc[5][1] = fmaf(a1.y, xv.y, acc[5][1]);
        acc[5][2] = fmaf(a1.y, xv.z, acc[5][2]);
        acc[5][3] = fmaf(a1.y, xv.w, acc[5][3]);
        acc[6][0] = fmaf(a1.z, xv.x, acc[6][0]);
        acc[6][1] = fmaf(a1.z, xv.y, acc[6][1]);
        acc[6][2] = fmaf(a1.z, xv.z, acc[6][2]);
        acc[6][3] = fmaf(a1.z, xv.w, acc[6][3]);
        acc[7][0] = fmaf(a1.w, xv.x, acc[7][0]);
        acc[7][1] = fmaf(a1.w, xv.y, acc[7][1]);
        acc[7][2] = fmaf(a1.w, xv.z, acc[7][2]);
        acc[7][3] = fmaf(a1.w, xv.w, acc[7][3]);
    }
#pragma unroll
    for (int o = 0; o < 8; o++)
        *reinterpret_cast<float4*>(&Tp[team][o][t64 * 4]) =
            make_float4(acc[o][0], acc[o][1], acc[o][2], acc[o][3]);
    __syncthreads();

    float* TsF = &Tp[0][0][0];   // Ts[o][c] = TsF[o*256 + c]
    {
        float s[8];
#pragma unroll
        for (int o = 0; o < 8; o++)
            s[o] = Tp[0][o][tid] + Tp[1][o][tid] + Tp[2][o][tid] + Tp[3][o][tid];
#pragma unroll
        for (int o = 0; o < 8; o++) TsF[o * 256 + tid] = s[o];
    }
    __syncthreads();

    if (tid < 64) {
        const int oy = tid >> 3, ox = tid & 7;
        const float* tsr = TsF + oy * 256;
        float s = 0.0f;
#pragma unroll 8
        for (int j = 0; j < 256; j++)
            s = fmaf(tsr[j], As[j][ox], s);
        g_dct[blk * 64 + tid] = s;
    } else if (tid < 128) {
        const int cl = tid - 64;
        const int r = 32 * (cl >> 3) + 15;
        const int c = 32 * (cl & 7) + 15;
        float p[4][4];
#pragma unroll
        for (int a = 0; a < 4; a++)
#pragma unroll
            for (int b = 0; b < 4; b++)
                p[a][b] = xc[(r - 1 + a) * 256 + (c - 1 + b)];
        float gsum = 0.0f;
#pragma unroll
        for (int i = 0; i < 2; i++)
#pragma unroll
            for (int j = 0; j < 2; j++) {
                float gx = (p[i][j + 2] - p[i][j])
                         + 2.0f * (p[i + 1][j + 2] - p[i + 1][j])
                         + (p[i + 2][j + 2] - p[i + 2][j]);
                float gy = (p[i + 2][j] - p[i][j])
                         + 2.0f * (p[i + 2][j + 1] - p[i][j + 1])
                         + (p[i + 2][j + 2] - p[i][j + 2]);
                gsum += sqrtf(gx * gx + gy * gy);
            }
        g_grad[blk * 64 + cl] = 0.25f * gsum;
    }
}

// ---------------------------------------------------------------------------
// Kernel 2a: conv3x3 + BN + ReLU partials. grid = 1024 (128 b x 8 groups),
// block = 256. Writes transposed g_part[j][bidx].
// ---------------------------------------------------------------------------
__global__ void __launch_bounds__(256) head_part_kernel(
    const float* __restrict__ cw_d, const float* __restrict__ cb_d,
    const float* __restrict__ bg_d, const float* __restrict__ bb_d,
    const float* __restrict__ cw_g, const float* __restrict__ cb_g,
    const float* __restrict__ bg_g, const float* __restrict__ bb_g,
    const float* __restrict__ fw, const float* __restrict__ clsw)
{
    __shared__ float tile[2][3][10][10];
    __shared__ float wsm[2][8][28];
    __shared__ float bnc[2][8][2];
    __shared__ float fws[8];
    __shared__ float wred[8][5];

    const int bidx = blockIdx.x;
    const int b = bidx >> 3, grp = bidx & 7;
    const int tid = threadIdx.x;

    for (int t = tid; t < 432; t += 256) {
        int br = t / 216, r = t % 216;
        int lc = r / 27, i = r % 27;
        const float* w = br ? cw_g : cw_d;
        wsm[br][lc][i] = w[(grp * 8 + lc) * 27 + i];
    }
    if (tid < 16) {
        int br = tid >> 3, lc = tid & 7, ch = grp * 8 + lc;
        const float rs = rsqrtf(1.0f + 1e-5f);
        float k = (br ? bg_g[ch] : bg_d[ch]) * rs;
        float bb = (br ? cb_g[ch] : cb_d[ch]) * k + (br ? bb_g[ch] : bb_d[ch]);
        bnc[br][lc][0] = k; bnc[br][lc][1] = bb;
    } else if (tid < 24) {
        fws[tid - 16] = fw[grp * 8 + (tid - 16)];
    }
    for (int t = tid; t < 600; t += 256) {
        int br = t / 300, rem = t % 300;
        int c = rem / 100, yy = (rem % 100) / 10, xx = rem % 10;
        float v = 0.0f;
        if (yy >= 1 && yy <= 8 && xx >= 1 && xx <= 8) {
            const float* src = br ? g_grad : g_dct;
            v = src[(b * 3 + c) * 64 + (yy - 1) * 8 + (xx - 1)];
        }
        tile[br][c][yy][xx] = v;
    }
    __syncthreads();

    const int lch = tid >> 5;
    const int c32 = tid & 31;
    const int ch = grp * 8 + lch;

    const float kd = bnc[0][lch][0], bd = bnc[0][lch][1];
    const float kg = bnc[1][lch][0], bg = bnc[1][lch][1];

    float s_acc = 0.f, D0 = 0.f, D1 = 0.f, G0 = 0.f, G1 = 0.f;
#pragma unroll
    for (int half = 0; half < 2; half++) {
        int cell = c32 + half * 32;
        int oy = cell >> 3, ox = cell & 7;
        float ad = 0.f, ag = 0.f;
#pragma unroll
        for (int ci = 0; ci < 3; ci++)
#pragma unroll
            for (int ky = 0; ky < 3; ky++)
#pragma unroll
                for (int kx = 0; kx < 3; kx++) {
                    float tv0 = tile[0][ci][oy + ky][ox + kx];
                    float tv1 = tile[1][ci][oy + ky][ox + kx];
                    ad = fmaf(tv0, wsm[0][lch][ci * 9 + ky * 3 + kx], ad);
                    ag = fmaf(tv1, wsm[1][lch][ci * 9 + ky * 3 + kx], ag);
                }
        float d = fmaxf(fmaf(ad, kd, bd), 0.0f);
        float g = fmaxf(fmaf(ag, kg, bg), 0.0f);
        s_acc += d + g;
        int flat = ch * 64 + cell;
        float w0 = clsw[flat], w1 = clsw[4096 + flat];
        D0 = fmaf(d, w0, D0); D1 = fmaf(d, w1, D1);
        G0 = fmaf(g, w0, G0); G1 = fmaf(g, w1, G1);
    }
    s_acc *= fws[lch];

#pragma unroll
    for (int off = 16; off > 0; off >>= 1) {
        s_acc += __shfl_down_sync(0xffffffffu, s_acc, off);
        D0 += __shfl_down_sync(0xffffffffu, D0, off);
        D1 += __shfl_down_sync(0xffffffffu, D1, off);
        G0 += __shfl_down_sync(0xffffffffu, G0, off);
        G1 += __shfl_down_sync(0xffffffffu, G1, off);
    }
    if ((tid & 31) == 0) {
        int w = tid >> 5;
        wred[w][0] = s_acc; wred[w][1] = D0; wred[w][2] = D1;
        wred[w][3] = G0; wred[w][4] = G1;
    }
    __syncthreads();
    if (tid < 5) {
        float s = 0.f;
#pragma unroll
        for (int w = 0; w < 8; w++) s += wred[w][tid];
        g_part[tid][bidx] = s;          // transposed layout
    }
}

// ---------------------------------------------------------------------------
// Kernel 2b: gate + final combine. grid = 128 (one block per batch), block = 32.
// Lane l: group = l&7, partial j = l>>3 (j<4 used for first 4; j=4 via lane reuse).
// Simpler: each of 8 lanes handles one group and loads all 5 partials; shuffle-sum.
// ---------------------------------------------------------------------------
__global__ void __launch_bounds__(32) head_final_kernel(
    const float* __restrict__ fb, const float* __restrict__ clsb,
    float* __restrict__ out)
{
    const int b = blockIdx.x;
    const int lane = threadIdx.x;
    float v[5] = {0.f, 0.f, 0.f, 0.f, 0.f};
    if (lane < 8) {
#pragma unroll
        for (int j = 0; j < 5; j++) v[j] = g_part[j][b * 8 + lane];
    }
#pragma unroll
    for (int j = 0; j < 5; j++) {
        v[j] += __shfl_xor_sync(0xffffffffu, v[j], 1);
        v[j] += __shfl_xor_sync(0xffffffffu, v[j], 2);
        v[j] += __shfl_xor_sync(0xffffffffu, v[j], 4);
    }
    if (lane == 0) {
        float w = 1.0f / (1.0f + expf(-(v[0] * (1.0f / 64.0f) + fb[0])));
        out[b * 2 + 0] = w * v[1] + (1.0f - w) * v[3] + clsb[0];
        out[b * 2 + 1] = w * v[2] + (1.0f - w) * v[4] + clsb[1];
    }
}

// ---------------------------------------------------------------------------
extern "C" void kernel_launch(void* const* d_in, const int* in_sizes, int n_in,
                              void* d_out, int out_size) {
    const float* x     = (const float*)d_in[0];
    const float* cw_d  = (const float*)d_in[1];
    const float* cb_d  = (const float*)d_in[2];
    const float* bg_d  = (const float*)d_in[3];
    const float* bb_d  = (const float*)d_in[4];
    const float* cw_g  = (const float*)d_in[5];
    const float* cb_g  = (const float*)d_in[6];
    const float* bg_g  = (const float*)d_in[7];
    const float* bb_g  = (const float*)d_in[8];
    const float* fw    = (const float*)d_in[9];
    const float* fb    = (const float*)d_in[10];
    const float* clsw  = (const float*)d_in[11];
    const float* clsb  = (const float*)d_in[12];
    float* out = (float*)d_out;

    setupA_kernel<<<8, 256>>>();
    dct_grad_kernel<<<384, 256>>>(x);
    head_part_kernel<<<1024, 256>>>(cw_d, cb_d, bg_d, bb_d,
                                    cw_g, cb_g, bg_g, bb_g, fw, clsw);
    head_final_kernel<<<128, 32>>>(fb, clsb, out);
}